// round 10
// baseline (speedup 1.0000x reference)
#include <cuda_runtime.h>
#include <stdint.h>

// SGC 2-hop: out = S^2 x W^T + b,  S = D^-1/2 (A + I) D^-1/2
// Identity: (S^2 x) W^T == S^2 (x W^T) -> project features to scalar FIRST,
// then two scalar scatter passes over edges (L2-resident accumulators).
// R9: PROWS=16 (project fully bandwidth-bound), scatter EPT=2 (occupancy).

#define MAXN  100000
#define MAXE  600000
#define DFEAT 128
#define PROWS 16         // rows per warp in k_project
#define EPT   2          // edges per thread in k_scatter (one int4)

__device__ int   g_cnt[MAXN];     // in-degree (excl. self loop)
__device__ float g_dis[MAXN];     // deg^-1/2
__device__ float g_z[MAXN];       // scalar being propagated
__device__ float g_acc[MAXN];     // scatter accumulator
__device__ int2  g_edge[MAXE];    // packed (row, col) int32
__device__ int   g_is32;          // zero-init at load; sticky (set-to-1 only)

__device__ __forceinline__ int load_idx(const void* ei, int is32, long long pos) {
    if (is32) return __ldg((const int*)ei + pos);
    return (int)__ldg((const long long*)ei + pos);
}

// ---- kernel 0: zero counts; first 2048 threads also detect index dtype on a
// 4096-word prefix. int64 LE (<2^31) => odd 32-bit words all 0; real int32
// indices make this essentially impossible. Sticky flag => deterministic.
__global__ void k_init_detect(const int* __restrict__ w, int e, int n) {
    int i = blockIdx.x * blockDim.x + threadIdx.x;
    if (i < n) g_cnt[i] = 0;
    if (i < 2048) {
        long long lim = 2LL * e;
        long long p = 2LL * i + 1;
        if (p < lim && __ldg(w + p) != 0) g_is32 = 1;
    }
}

// ---- kernel 1: pack (row,col) into int2 scratch + count in-degree ----
__global__ void k_pack_count(const void* __restrict__ ei, int e, int n) {
    int i = blockIdx.x * blockDim.x + threadIdx.x;
    if (i >= e) return;
    int is32 = g_is32;
    int r = load_idx(ei, is32, i);
    int c = load_idx(ei, is32, (long long)e + i);
    g_edge[i] = make_int2(r, c);
    if ((unsigned)c < (unsigned)n) atomicAdd(&g_cnt[c], 1);
}

// ---- kernel 2: y = x @ W^T, 16 rows/warp (MLP=16); z = dis*y; acc = z ----
__global__ void k_project(const float* __restrict__ x,
                          const float* __restrict__ W, int n) {
    int warp = (blockIdx.x * blockDim.x + threadIdx.x) >> 5;
    int lane = threadIdx.x & 31;
    int base = warp * PROWS;
    if (base >= n) return;

    int rows = n - base; if (rows > PROWS) rows = PROWS;

    float4 w = reinterpret_cast<const float4*>(W)[lane];
    const float4* xv = reinterpret_cast<const float4*>(x)
                       + (size_t)base * (DFEAT / 4) + lane;

    float4 a[PROWS];
    #pragma unroll
    for (int j = 0; j < PROWS; j++)
        if (j < rows) a[j] = xv[(size_t)j * (DFEAT / 4)];

    #pragma unroll
    for (int j = 0; j < PROWS; j++) {
        if (j >= rows) break;
        float d = a[j].x * w.x + a[j].y * w.y + a[j].z * w.z + a[j].w * w.w;
        #pragma unroll
        for (int off = 16; off > 0; off >>= 1)
            d += __shfl_down_sync(0xFFFFFFFFu, d, off);
        if (lane == 0) {
            int node = base + j;
            float dis = rsqrtf((float)(g_cnt[node] + 1));  // +1 self loop
            float z = dis * d;
            g_dis[node] = dis;
            g_z[node]   = z;
            g_acc[node] = z;   // self-loop contribution
        }
    }
}

// ---- kernel 3: acc[col] += z[row], 2 edges/thread (one int4 load) ----
__global__ void k_scatter(int e, int n) {
    int t = blockIdx.x * blockDim.x + threadIdx.x;
    int base = t * EPT;
    if (base >= e) return;

    int4 p = __ldg(reinterpret_cast<const int4*>(&g_edge[base]));
    int r0 = p.x, c0 = p.y;
    int r1 = p.z, c1 = p.w;
    if (base + 1 >= e) c1 = -1;   // tail guard

    float v0 = ((unsigned)r0 < (unsigned)n && (unsigned)c0 < (unsigned)n)
               ? __ldg(&g_z[r0]) : 0.0f;
    float v1 = ((unsigned)r1 < (unsigned)n && (unsigned)c1 < (unsigned)n)
               ? __ldg(&g_z[r1]) : 0.0f;

    if ((unsigned)c0 < (unsigned)n && v0 != 0.0f) atomicAdd(&g_acc[c0], v0);
    if ((unsigned)c1 < (unsigned)n && v1 != 0.0f) atomicAdd(&g_acc[c1], v1);
}

// ---- kernel 4: z' = dis^2 * acc; acc = z' (self loop for next hop) ----
__global__ void k_rescale(int n) {
    int i = blockIdx.x * blockDim.x + threadIdx.x;
    if (i < n) {
        float dis = g_dis[i];
        float v = dis * dis * g_acc[i];
        g_z[i]   = v;
        g_acc[i] = v;
    }
}

// ---- kernel 5: out = dis * acc + b ----
__global__ void k_finish(float* __restrict__ out,
                         const float* __restrict__ b, int n) {
    int i = blockIdx.x * blockDim.x + threadIdx.x;
    if (i < n) out[i] = g_dis[i] * g_acc[i] + b[0];
}

extern "C" void kernel_launch(void* const* d_in, const int* in_sizes, int n_in,
                              void* d_out, int out_size) {
    const float* x  = (const float*)d_in[0];
    const void*  ei = d_in[1];                 // [2, E], int32 or int64
    const float* W  = (const float*)d_in[2];
    const float* b  = (const float*)d_in[3];
    float* out = (float*)d_out;

    int n = in_sizes[0] / DFEAT;      // 100000
    int e = in_sizes[1] / 2;          // 600000
    if (e > MAXE) e = MAXE;           // scratch capacity guard

    const int T = 256;
    int gbN = (n + T - 1) / T;
    int gbE = (e + T - 1) / T;
    int nwarps = (n + PROWS - 1) / PROWS;
    int gbP = (nwarps * 32 + T - 1) / T;
    int nse = (e + EPT - 1) / EPT;
    int gbS = (nse + T - 1) / T;

    k_init_detect<<<gbN, T>>>((const int*)ei, e, n);
    k_pack_count <<<gbE, T>>>(ei, e, n);
    k_project    <<<gbP, T>>>(x, W, n);
    k_scatter    <<<gbS, T>>>(e, n);   // hop 1
    k_rescale    <<<gbN, T>>>(n);
    k_scatter    <<<gbS, T>>>(e, n);   // hop 2
    k_finish     <<<gbN, T>>>(out, b, n);
}

// round 13
// speedup vs baseline: 1.4541x; 1.4541x over previous
#include <cuda_runtime.h>
#include <stdint.h>

// SGC 2-hop: out = S^2 x W^T + b,  S = D^-1/2 (A + I) D^-1/2
// Identity: (S^2 x) W^T == S^2 (x W^T) -> project features to scalar FIRST,
// then two scalar scatter passes over edges (L2-resident accumulators).
// R10: revert to measured-best R7 shape (PROWS=8, direct EPT=1 scatter),
//      keep only the prefix dtype-detect (saves a 9.6MB streaming pass).

#define MAXN  100000
#define DFEAT 128
#define PROWS 8          // rows per warp in k_project (measured best)

__device__ int   g_cnt[MAXN];   // in-degree (excl. self loop)
__device__ float g_dis[MAXN];   // deg^-1/2
__device__ float g_z[MAXN];     // scalar being propagated
__device__ float g_acc[MAXN];   // scatter accumulator
__device__ int   g_is32;        // zero-init at load; sticky (set-to-1 only)

__device__ __forceinline__ int load_idx(const void* ei, int is32, long long pos) {
    if (is32) return __ldg((const int*)ei + pos);
    return (int)__ldg((const long long*)ei + pos);
}

// ---- kernel 0: zero counts; first 2048 threads detect index dtype on a
// 4096-word prefix. int64 LE (<2^31) => odd 32-bit words all 0; genuine
// random int32 indices hit a nonzero odd word with P ~ 1 - 1e-5 per word.
// Sticky flag (never reset) => deterministic across graph replays.
__global__ void k_init_detect(const int* __restrict__ w, int e, int n) {
    int i = blockIdx.x * blockDim.x + threadIdx.x;
    if (i < n) g_cnt[i] = 0;
    if (i < 2048) {
        long long lim = 2LL * e;
        long long p = 2LL * i + 1;
        if (p < lim && __ldg(w + p) != 0) g_is32 = 1;
    }
}

// ---- kernel 1: count in-degree over col ----
__global__ void k_count(const void* __restrict__ ei, int e, int n) {
    int i = blockIdx.x * blockDim.x + threadIdx.x;
    if (i >= e) return;
    int c = load_idx(ei, g_is32, (long long)e + i);
    if ((unsigned)c < (unsigned)n) atomicAdd(&g_cnt[c], 1);
}

// ---- kernel 2: y = x @ W^T, 8 rows/warp (MLP=8); z = dis*y; acc = z ----
__global__ void k_project(const float* __restrict__ x,
                          const float* __restrict__ W, int n) {
    int warp = (blockIdx.x * blockDim.x + threadIdx.x) >> 5;
    int lane = threadIdx.x & 31;
    int base = warp * PROWS;
    if (base >= n) return;

    int rows = n - base; if (rows > PROWS) rows = PROWS;

    float4 w = reinterpret_cast<const float4*>(W)[lane];
    const float4* xv = reinterpret_cast<const float4*>(x)
                       + (size_t)base * (DFEAT / 4) + lane;

    float4 a[PROWS];
    #pragma unroll
    for (int j = 0; j < PROWS; j++)
        if (j < rows) a[j] = xv[(size_t)j * (DFEAT / 4)];

    #pragma unroll
    for (int j = 0; j < PROWS; j++) {
        if (j >= rows) break;
        float d = a[j].x * w.x + a[j].y * w.y + a[j].z * w.z + a[j].w * w.w;
        #pragma unroll
        for (int off = 16; off > 0; off >>= 1)
            d += __shfl_down_sync(0xFFFFFFFFu, d, off);
        if (lane == 0) {
            int node = base + j;
            float dis = rsqrtf((float)(g_cnt[node] + 1));  // +1 self loop
            float z = dis * d;
            g_dis[node] = dis;
            g_z[node]   = z;
            g_acc[node] = z;   // self-loop contribution
        }
    }
}

// ---- kernel 3: acc[col] += z[row]  (1 edge/thread — measured best) ----
__global__ void k_scatter(const void* __restrict__ ei, int e, int n) {
    int i = blockIdx.x * blockDim.x + threadIdx.x;
    if (i >= e) return;
    int is32 = g_is32;
    int r = load_idx(ei, is32, i);
    int c = load_idx(ei, is32, (long long)e + i);
    if ((unsigned)r < (unsigned)n && (unsigned)c < (unsigned)n)
        atomicAdd(&g_acc[c], __ldg(&g_z[r]));
}

// ---- kernel 4: z' = dis^2 * acc; acc = z' (self loop for next hop) ----
__global__ void k_rescale(int n) {
    int i = blockIdx.x * blockDim.x + threadIdx.x;
    if (i < n) {
        float dis = g_dis[i];
        float v = dis * dis * g_acc[i];
        g_z[i]   = v;
        g_acc[i] = v;
    }
}

// ---- kernel 5: out = dis * acc + b ----
__global__ void k_finish(float* __restrict__ out,
                         const float* __restrict__ b, int n) {
    int i = blockIdx.x * blockDim.x + threadIdx.x;
    if (i < n) out[i] = g_dis[i] * g_acc[i] + b[0];
}

extern "C" void kernel_launch(void* const* d_in, const int* in_sizes, int n_in,
                              void* d_out, int out_size) {
    const float* x  = (const float*)d_in[0];
    const void*  ei = d_in[1];                 // [2, E], int32 or int64
    const float* W  = (const float*)d_in[2];
    const float* b  = (const float*)d_in[3];
    float* out = (float*)d_out;

    int n = in_sizes[0] / DFEAT;      // 100000
    int e = in_sizes[1] / 2;          // 600000

    const int T = 256;
    int gbN = (n + T - 1) / T;
    int gbE = (e + T - 1) / T;
    int nwarps = (n + PROWS - 1) / PROWS;
    int gbP = (nwarps * 32 + T - 1) / T;

    k_init_detect<<<gbN, T>>>((const int*)ei, e, n);
    k_count      <<<gbE, T>>>(ei, e, n);
    k_project    <<<gbP, T>>>(x, W, n);
    k_scatter    <<<gbE, T>>>(ei, e, n);   // hop 1
    k_rescale    <<<gbN, T>>>(n);
    k_scatter    <<<gbE, T>>>(ei, e, n);   // hop 2
    k_finish     <<<gbN, T>>>(out, b, n);
}

// round 15
// speedup vs baseline: 1.5563x; 1.0703x over previous
#include <cuda_runtime.h>
#include <stdint.h>

// SGC 2-hop: out = S^2 x W^T + b,  S = D^-1/2 (A + I) D^-1/2
// Identity: (S^2 x) W^T == S^2 (x W^T) -> project to scalar FIRST.
// R13: S^2 = D^-1/2 (A+I) D^-1 (A+I) D^-1/2  => raw projection y = xW^T
// needs no degrees, so degree-count is FUSED into the projection kernel
// (disjoint thread ranges: DRAM-bound stream + LSU-bound atomics overlap).

#define MAXN  100000
#define DFEAT 128
#define PROWS 8          // rows per warp in projection (measured best)

__device__ int   g_cnt[MAXN];   // in-degree (excl. self loop)
__device__ float g_y[MAXN];     // raw projection x @ W^T
__device__ float g_dis[MAXN];   // deg^-1/2
__device__ float g_z[MAXN];     // scalar being propagated
__device__ float g_acc[MAXN];   // scatter accumulator
__device__ int   g_is32;        // zero-init at load; sticky (set-to-1 only)

__device__ __forceinline__ int load_idx(const void* ei, int is32, long long pos) {
    if (is32) return __ldg((const int*)ei + pos);
    return (int)__ldg((const long long*)ei + pos);
}

// ---- kernel 0: zero counts; first 2048 threads detect index dtype on a
// 4096-word prefix (int64 LE < 2^31 => odd words all zero; random int32
// indices defeat this with P ~ 1-1e-5 per word). Sticky => deterministic.
__global__ void k_init_detect(const int* __restrict__ w, int e, int n) {
    int i = blockIdx.x * blockDim.x + threadIdx.x;
    if (i < n) g_cnt[i] = 0;
    if (i < 2048) {
        long long lim = 2LL * e;
        long long p = 2LL * i + 1;
        if (p < lim && __ldg(w + p) != 0) g_is32 = 1;
    }
}

// ---- kernel 1 (fused): threads [0, pthreads) project y = x @ W^T
//      (8 rows/warp, MLP=8); threads [pthreads, pthreads+e) count in-degree.
__global__ void k_project_count(const float* __restrict__ x,
                                const float* __restrict__ W,
                                const void* __restrict__ ei,
                                int n, int e, int pthreads) {
    int gid = blockIdx.x * blockDim.x + threadIdx.x;

    if (gid < pthreads) {
        int warp = gid >> 5;
        int lane = gid & 31;
        int base = warp * PROWS;
        if (base >= n) return;
        int rows = n - base; if (rows > PROWS) rows = PROWS;

        float4 w = reinterpret_cast<const float4*>(W)[lane];
        const float4* xv = reinterpret_cast<const float4*>(x)
                           + (size_t)base * (DFEAT / 4) + lane;
        float4 a[PROWS];
        #pragma unroll
        for (int j = 0; j < PROWS; j++)
            if (j < rows) a[j] = xv[(size_t)j * (DFEAT / 4)];

        #pragma unroll
        for (int j = 0; j < PROWS; j++) {
            if (j >= rows) break;
            float d = a[j].x * w.x + a[j].y * w.y + a[j].z * w.z + a[j].w * w.w;
            #pragma unroll
            for (int off = 16; off > 0; off >>= 1)
                d += __shfl_down_sync(0xFFFFFFFFu, d, off);
            if (lane == 0) g_y[base + j] = d;
        }
    } else {
        int i = gid - pthreads;
        if (i >= e) return;
        int c = load_idx(ei, g_is32, (long long)e + i);
        if ((unsigned)c < (unsigned)n) atomicAdd(&g_cnt[c], 1);
    }
}

// ---- kernel 2: dis = rsqrt(deg); z = dis*y; acc = z (self loop) ----
__global__ void k_prep(int n) {
    int i = blockIdx.x * blockDim.x + threadIdx.x;
    if (i < n) {
        float dis = rsqrtf((float)(g_cnt[i] + 1));  // +1 self loop
        float z = dis * g_y[i];
        g_dis[i] = dis;
        g_z[i]   = z;
        g_acc[i] = z;
    }
}

// ---- kernel 3: acc[col] += z[row]  (1 edge/thread — measured best) ----
__global__ void k_scatter(const void* __restrict__ ei, int e, int n) {
    int i = blockIdx.x * blockDim.x + threadIdx.x;
    if (i >= e) return;
    int is32 = g_is32;
    int r = load_idx(ei, is32, i);
    int c = load_idx(ei, is32, (long long)e + i);
    if ((unsigned)r < (unsigned)n && (unsigned)c < (unsigned)n)
        atomicAdd(&g_acc[c], __ldg(&g_z[r]));
}

// ---- kernel 4: z' = dis^2 * acc; acc = z' (self loop for next hop) ----
__global__ void k_rescale(int n) {
    int i = blockIdx.x * blockDim.x + threadIdx.x;
    if (i < n) {
        float dis = g_dis[i];
        float v = dis * dis * g_acc[i];
        g_z[i]   = v;
        g_acc[i] = v;
    }
}

// ---- kernel 5: out = dis * acc + b ----
__global__ void k_finish(float* __restrict__ out,
                         const float* __restrict__ b, int n) {
    int i = blockIdx.x * blockDim.x + threadIdx.x;
    if (i < n) out[i] = g_dis[i] * g_acc[i] + b[0];
}

extern "C" void kernel_launch(void* const* d_in, const int* in_sizes, int n_in,
                              void* d_out, int out_size) {
    const float* x  = (const float*)d_in[0];
    const void*  ei = d_in[1];                 // [2, E], int32 or int64
    const float* W  = (const float*)d_in[2];
    const float* b  = (const float*)d_in[3];
    float* out = (float*)d_out;

    int n = in_sizes[0] / DFEAT;      // 100000
    int e = in_sizes[1] / 2;          // 600000

    const int T = 256;
    int gbN = (n + T - 1) / T;
    int gbE = (e + T - 1) / T;

    int nwarps = (n + PROWS - 1) / PROWS;
    int pthreads = ((nwarps * 32 + T - 1) / T) * T;   // block-aligned
    int total = pthreads + e;
    int gbF = (total + T - 1) / T;

    k_init_detect  <<<gbN, T>>>((const int*)ei, e, n);
    k_project_count<<<gbF, T>>>(x, W, ei, n, e, pthreads);
    k_prep         <<<gbN, T>>>(n);
    k_scatter      <<<gbE, T>>>(ei, e, n);   // hop 1
    k_rescale      <<<gbN, T>>>(n);
    k_scatter      <<<gbE, T>>>(ei, e, n);   // hop 2
    k_finish       <<<gbN, T>>>(out, b, n);
}